// round 13
// baseline (speedup 1.0000x reference)
#include <cuda_runtime.h>
#include <cuda_fp16.h>
#include <cstdint>

#define BATCH 256
#define OUTF  1024
#define INF   1024

// ---------------- device scratch (no allocs allowed) ----------------
__device__ int g_flag = 0;   // monotonic: 0 = fast path valid
__device__ __half g_phi_h[BATCH * INF];
__device__ __half g_w_h[OUTF * INF];

// ---------------- helpers ----------------
__device__ __forceinline__ uint32_t smem_u32(const void* p) {
    uint32_t a;
    asm("{ .reg .u64 t; cvta.to.shared.u64 t, %1; cvt.u32.u64 %0, t; }"
        : "=r"(a) : "l"(p));
    return a;
}

__device__ __forceinline__ void cp_async16(uint32_t dst, const void* src) {
    asm volatile("cp.async.cg.shared.global [%0], [%1], 16;"
                 :: "r"(dst), "l"(src) : "memory");
}
#define CP_COMMIT() asm volatile("cp.async.commit_group;" ::: "memory")
#define CP_WAIT(n)  asm volatile("cp.async.wait_group %0;" :: "n"(n) : "memory")

__device__ __forceinline__ void ldm_x4(uint32_t& r0, uint32_t& r1,
                                       uint32_t& r2, uint32_t& r3,
                                       uint32_t addr) {
    asm volatile("ldmatrix.sync.aligned.m8n8.x4.shared.b16 {%0,%1,%2,%3}, [%4];"
                 : "=r"(r0), "=r"(r1), "=r"(r2), "=r"(r3) : "r"(addr));
}

__device__ __forceinline__ void mma16816(float* c, const uint32_t* a,
                                         const uint32_t* b) {
    asm volatile(
        "mma.sync.aligned.m16n8k16.row.col.f32.f16.f16.f32 "
        "{%0,%1,%2,%3}, {%4,%5,%6,%7}, {%8,%9}, {%0,%1,%2,%3};"
        : "+f"(c[0]), "+f"(c[1]), "+f"(c[2]), "+f"(c[3])
        : "r"(a[0]), "r"(a[1]), "r"(a[2]), "r"(a[3]), "r"(b[0]), "r"(b[1]));
}

// pack 8 floats -> uint4 of fp16 (rn)
__device__ __forceinline__ uint4 pack8_h(const float4& a, const float4& b) {
    __half2 h0 = __floats2half2_rn(a.x, a.y);
    __half2 h1 = __floats2half2_rn(a.z, a.w);
    __half2 h2 = __floats2half2_rn(b.x, b.y);
    __half2 h3 = __floats2half2_rn(b.z, b.w);
    return make_uint4(*(uint32_t*)&h0, *(uint32_t*)&h1,
                      *(uint32_t*)&h2, *(uint32_t*)&h3);
}

__device__ __forceinline__ float dog(float x, float t, float s) {
    float z = (x - t) / s;
    return -z * __expf(-0.5f * z * z);
}

// ---------------- fused prep: check + W->fp16 + phi->fp16 ----------------
#define W_BLOCKS   ((OUTF * INF / 8) / 256)    // 512
#define PHI_BLOCKS ((BATCH * INF / 8) / 256)   // 128

__global__ __launch_bounds__(256)
void prep_kernel(const float4* __restrict__ w,
                 const float4* __restrict__ x,
                 const float4* __restrict__ scale,
                 const float4* __restrict__ trans) {
    if (blockIdx.x < W_BLOCKS) {
        int j = (blockIdx.x * 256 + threadIdx.x) * 2;
        int i40 = j & (INF / 4 - 1);
        int i41 = (j + 1) & (INF / 4 - 1);

        float4 w0 = w[j],     w1 = w[j + 1];
        float4 s0 = scale[j], s1 = scale[j + 1];
        float4 t0 = trans[j], t1 = trans[j + 1];
        float4 rs0 = scale[i40], rs1 = scale[i41];
        float4 rt0 = trans[i40], rt1 = trans[i41];

        bool bad =
            (s0.x != rs0.x) | (s0.y != rs0.y) | (s0.z != rs0.z) | (s0.w != rs0.w) |
            (s1.x != rs1.x) | (s1.y != rs1.y) | (s1.z != rs1.z) | (s1.w != rs1.w) |
            (t0.x != rt0.x) | (t0.y != rt0.y) | (t0.z != rt0.z) | (t0.w != rt0.w) |
            (t1.x != rt1.x) | (t1.y != rt1.y) | (t1.z != rt1.z) | (t1.w != rt1.w);
        if (bad) atomicOr(&g_flag, 1);

        reinterpret_cast<uint4*>(g_w_h)[j >> 1] = pack8_h(w0, w1);
    } else {
        int j = ((blockIdx.x - W_BLOCKS) * 256 + threadIdx.x) * 2;
        int i40 = j & (INF / 4 - 1);
        int i41 = (j + 1) & (INF / 4 - 1);
        float4 x0 = x[j], x1 = x[j + 1];
        float4 s0 = scale[i40], s1 = scale[i41];
        float4 t0 = trans[i40], t1 = trans[i41];
        float4 p0, p1;
        p0.x = dog(x0.x, t0.x, s0.x);
        p0.y = dog(x0.y, t0.y, s0.y);
        p0.z = dog(x0.z, t0.z, s0.z);
        p0.w = dog(x0.w, t0.w, s0.w);
        p1.x = dog(x1.x, t1.x, s1.x);
        p1.y = dog(x1.y, t1.y, s1.y);
        p1.z = dog(x1.z, t1.z, s1.z);
        p1.w = dog(x1.w, t1.w, s1.w);
        reinterpret_cast<uint4*>(g_phi_h)[j >> 1] = pack8_h(p0, p1);
    }
}

// ---------------- fp16 mma.sync GEMM (+ exact fallback branch) ----------
// out(256,1024) = phi @ W^T, single-pass fp16, f32 accumulate.
// CTA tile 32x64, 256 threads (8 warps, 2m x 4n), warp tile 16x16.
// BK=256 -> 4 chunks, one __syncthreads per chunk, 3-stage cp.async.
#define BM 32
#define BN 64
#define BK 256
#define NCHUNK (INF / BK)            // 4
#define ROWB    528                  // 256 fp16 = 512B + 16B pad
#define A_TILE  (BM * ROWB)          // 16896
#define B_TILE  (BN * ROWB)          // 33792
#define STAGEB  (A_TILE + B_TILE)    // 50688
#define NSTAGE  3
#define GEMM_SMEM (NSTAGE * STAGEB)  // 152064 (~148.5KB)

__global__ __launch_bounds__(256, 1)
void mma_gemm_kernel(float* __restrict__ out,
                     const float* __restrict__ x,
                     const float* __restrict__ w,
                     const float* __restrict__ s,
                     const float* __restrict__ t) {
    const int tid = threadIdx.x;
    const int m0 = blockIdx.y * BM;
    const int n0 = blockIdx.x * BN;

    if (g_flag) {
        // exact general path: 8 outputs per thread
        for (int e = tid; e < BM * BN; e += 256) {
            int b = m0 + (e >> 6);
            int o = n0 + (e & 63);
            const float* xr = x + (size_t)b * INF;
            const float* wr = w + (size_t)o * INF;
            const float* sr = s + (size_t)o * INF;
            const float* tr = t + (size_t)o * INF;
            float sum = 0.f;
            for (int i = 0; i < INF; ++i) {
                float z = (xr[i] - tr[i]) / sr[i];
                sum += wr[i] * (-z * __expf(-0.5f * z * z));
            }
            out[(size_t)b * OUTF + o] = sum;
        }
        return;
    }

    extern __shared__ char dsm[];
    const uint32_t sb = smem_u32(dsm);

    const int wid = tid >> 5, lid = tid & 31;
    const int wm = wid >> 2, wn = wid & 3;        // 2m x 4n warps, tile 16x16

    // per chunk: A 1024 + B 2048 = 3072 x 16B, 12 per thread
    auto load_chunk = [&](int ci, int stage) {
        const int kc = ci * BK;
        const uint32_t st = sb + stage * STAGEB;
        #pragma unroll
        for (int it = 0; it < 12; it++) {
            int idx = tid + it * 256;
            if (idx < 1024) {
                int r = idx >> 5;                // 0..31
                int q = idx & 31;                // 16B unit along k
                const __half* g = g_phi_h + (size_t)(m0 + r) * INF + kc + q * 8;
                cp_async16(st + r * ROWB + q * 16, g);
            } else {
                int idx2 = idx - 1024;
                int r = idx2 >> 5;               // 0..63
                int q = idx2 & 31;
                const __half* g = g_w_h + (size_t)(n0 + r) * INF + kc + q * 8;
                cp_async16(st + A_TILE + r * ROWB + q * 16, g);
            }
        }
        CP_COMMIT();
    };

    float acc[2][4] = {{0}};

    load_chunk(0, 0);
    load_chunk(1, 1);

    const int a_row = wm * 16 + (lid & 15);
    const int a_colq = (lid >> 4) * 8;
    const int b_row7 = (lid & 7);
    const int b_colq = (lid >> 3) * 8;           // 0,8,16,24 over k32

    for (int ci = 0; ci < NCHUNK; ci++) {
        if (ci + 1 < NCHUNK) { CP_WAIT(1); } else { CP_WAIT(0); }
        __syncthreads();   // publish chunk ci; retire stage (ci-1)%3

        if (ci + 2 < NCHUNK) load_chunk(ci + 2, (ci + 2) % NSTAGE);

        const uint32_t sA = sb + (ci % NSTAGE) * STAGEB;
        const uint32_t sB = sA + A_TILE;

        #pragma unroll
        for (int kh = 0; kh < BK / 32; kh++) {   // 8 k32 groups
            const int kb32 = kh * 32;
            uint32_t bfrag[2][4];
            #pragma unroll
            for (int nb = 0; nb < 2; nb++) {
                const int brow = wn * 16 + nb * 8 + b_row7;
                ldm_x4(bfrag[nb][0], bfrag[nb][1], bfrag[nb][2], bfrag[nb][3],
                       sB + brow * ROWB + (kb32 + b_colq) * 2);
            }
            #pragma unroll
            for (int ks = 0; ks < 2; ks++) {     // k16 steps within k32
                const int kb = kb32 + ks * 16;
                uint32_t afrag[4];
                ldm_x4(afrag[0], afrag[1], afrag[2], afrag[3],
                       sA + a_row * ROWB + (kb + a_colq) * 2);
                #pragma unroll
                for (int nb = 0; nb < 2; nb++)
                    mma16816(acc[nb], afrag, &bfrag[nb][ks * 2]);
            }
        }
    }

    const int row0 = m0 + wm * 16 + (lid >> 2);
    #pragma unroll
    for (int nb = 0; nb < 2; nb++) {
        const int col = n0 + wn * 16 + nb * 8 + (lid & 3) * 2;
        *reinterpret_cast<float2*>(&out[(size_t)row0 * OUTF + col]) =
            make_float2(acc[nb][0], acc[nb][1]);
        *reinterpret_cast<float2*>(&out[(size_t)(row0 + 8) * OUTF + col]) =
            make_float2(acc[nb][2], acc[nb][3]);
    }
}

extern "C" void kernel_launch(void* const* d_in, const int* in_sizes, int n_in,
                              void* d_out, int out_size) {
    const float* x     = (const float*)d_in[0];
    const float* wgt   = (const float*)d_in[1];
    const float* scale = (const float*)d_in[2];
    const float* trans = (const float*)d_in[3];
    float* out = (float*)d_out;

    static bool attr_set = false;
    if (!attr_set) {
        cudaFuncSetAttribute(mma_gemm_kernel,
                             cudaFuncAttributeMaxDynamicSharedMemorySize,
                             GEMM_SMEM);
        attr_set = true;
    }

    prep_kernel<<<W_BLOCKS + PHI_BLOCKS, 256>>>(
        (const float4*)wgt, (const float4*)x,
        (const float4*)scale, (const float4*)trans);
    mma_gemm_kernel<<<dim3(OUTF / BN, BATCH / BM), 256, GEMM_SMEM>>>(
        out, x, wgt, scale, trans);
}

// round 15
// speedup vs baseline: 1.0200x; 1.0200x over previous
#include <cuda_runtime.h>
#include <cuda_fp16.h>
#include <cstdint>

#define BATCH 256
#define OUTF  1024
#define INF   1024

// ---------------- device scratch (no allocs allowed) ----------------
__device__ int g_flag = 0;   // monotonic: 0 = fast path valid
__device__ __half g_phi_h[BATCH * INF];
__device__ __half g_w_h[OUTF * INF];

// ---------------- helpers ----------------
__device__ __forceinline__ uint32_t smem_u32(const void* p) {
    uint32_t a;
    asm("{ .reg .u64 t; cvta.to.shared.u64 t, %1; cvt.u32.u64 %0, t; }"
        : "=r"(a) : "l"(p));
    return a;
}

__device__ __forceinline__ void cp_async16(uint32_t dst, const void* src) {
    asm volatile("cp.async.cg.shared.global [%0], [%1], 16;"
                 :: "r"(dst), "l"(src) : "memory");
}
#define CP_COMMIT() asm volatile("cp.async.commit_group;" ::: "memory")
#define CP_WAIT(n)  asm volatile("cp.async.wait_group %0;" :: "n"(n) : "memory")

__device__ __forceinline__ void ldm_x4(uint32_t& r0, uint32_t& r1,
                                       uint32_t& r2, uint32_t& r3,
                                       uint32_t addr) {
    asm volatile("ldmatrix.sync.aligned.m8n8.x4.shared.b16 {%0,%1,%2,%3}, [%4];"
                 : "=r"(r0), "=r"(r1), "=r"(r2), "=r"(r3) : "r"(addr));
}

__device__ __forceinline__ void mma16816(float* c, const uint32_t* a,
                                         const uint32_t* b) {
    asm volatile(
        "mma.sync.aligned.m16n8k16.row.col.f32.f16.f16.f32 "
        "{%0,%1,%2,%3}, {%4,%5,%6,%7}, {%8,%9}, {%0,%1,%2,%3};"
        : "+f"(c[0]), "+f"(c[1]), "+f"(c[2]), "+f"(c[3])
        : "r"(a[0]), "r"(a[1]), "r"(a[2]), "r"(a[3]), "r"(b[0]), "r"(b[1]));
}

// pack 8 floats -> uint4 of fp16 (rn)
__device__ __forceinline__ uint4 pack8_h(const float4& a, const float4& b) {
    __half2 h0 = __floats2half2_rn(a.x, a.y);
    __half2 h1 = __floats2half2_rn(a.z, a.w);
    __half2 h2 = __floats2half2_rn(b.x, b.y);
    __half2 h3 = __floats2half2_rn(b.z, b.w);
    return make_uint4(*(uint32_t*)&h0, *(uint32_t*)&h1,
                      *(uint32_t*)&h2, *(uint32_t*)&h3);
}

__device__ __forceinline__ float dog(float x, float t, float s) {
    float z = (x - t) / s;
    return -z * __expf(-0.5f * z * z);
}

// ---------------- fused prep: check + W->fp16 + phi->fp16 ----------------
#define W_BLOCKS   ((OUTF * INF / 8) / 256)    // 512
#define PHI_BLOCKS ((BATCH * INF / 8) / 256)   // 128

__global__ __launch_bounds__(256)
void prep_kernel(const float4* __restrict__ w,
                 const float4* __restrict__ x,
                 const float4* __restrict__ scale,
                 const float4* __restrict__ trans) {
    if (blockIdx.x < W_BLOCKS) {
        int j = (blockIdx.x * 256 + threadIdx.x) * 2;
        int i40 = j & (INF / 4 - 1);
        int i41 = (j + 1) & (INF / 4 - 1);

        float4 w0 = w[j],     w1 = w[j + 1];
        float4 s0 = scale[j], s1 = scale[j + 1];
        float4 t0 = trans[j], t1 = trans[j + 1];
        float4 rs0 = scale[i40], rs1 = scale[i41];
        float4 rt0 = trans[i40], rt1 = trans[i41];

        bool bad =
            (s0.x != rs0.x) | (s0.y != rs0.y) | (s0.z != rs0.z) | (s0.w != rs0.w) |
            (s1.x != rs1.x) | (s1.y != rs1.y) | (s1.z != rs1.z) | (s1.w != rs1.w) |
            (t0.x != rt0.x) | (t0.y != rt0.y) | (t0.z != rt0.z) | (t0.w != rt0.w) |
            (t1.x != rt1.x) | (t1.y != rt1.y) | (t1.z != rt1.z) | (t1.w != rt1.w);
        if (bad) atomicOr(&g_flag, 1);

        reinterpret_cast<uint4*>(g_w_h)[j >> 1] = pack8_h(w0, w1);
    } else {
        int j = ((blockIdx.x - W_BLOCKS) * 256 + threadIdx.x) * 2;
        int i40 = j & (INF / 4 - 1);
        int i41 = (j + 1) & (INF / 4 - 1);
        float4 x0 = x[j], x1 = x[j + 1];
        float4 s0 = scale[i40], s1 = scale[i41];
        float4 t0 = trans[i40], t1 = trans[i41];
        float4 p0, p1;
        p0.x = dog(x0.x, t0.x, s0.x);
        p0.y = dog(x0.y, t0.y, s0.y);
        p0.z = dog(x0.z, t0.z, s0.z);
        p0.w = dog(x0.w, t0.w, s0.w);
        p1.x = dog(x1.x, t1.x, s1.x);
        p1.y = dog(x1.y, t1.y, s1.y);
        p1.z = dog(x1.z, t1.z, s1.z);
        p1.w = dog(x1.w, t1.w, s1.w);
        reinterpret_cast<uint4*>(g_phi_h)[j >> 1] = pack8_h(p0, p1);
    }
}

// ---------------- fp16 mma.sync GEMM (+ exact fallback branch) ----------
// out(256,1024) = phi @ W^T, single-pass fp16, f32 accumulate.
// CTA tile 32x64, 256 threads (8 warps, 2m x 4n), warp tile 16x16.
// BK=128 -> 8 chunks, one __syncthreads per chunk, 3-stage cp.async.
// NEW: acc split by k16 parity (4 chains/warp) + fragment double-buffering
// across k32 groups (LDSM overlapped with MMA issue).
#define BM 32
#define BN 64
#define BK 128
#define NCHUNK (INF / BK)            // 8
#define ROWB    272                  // 128 fp16 = 256B + 16B pad
#define A_TILE  (BM * ROWB)          // 8704
#define B_TILE  (BN * ROWB)          // 17408
#define STAGEB  (A_TILE + B_TILE)    // 26112
#define NSTAGE  3
#define GEMM_SMEM (NSTAGE * STAGEB)  // 78336

__global__ __launch_bounds__(256, 1)
void mma_gemm_kernel(float* __restrict__ out,
                     const float* __restrict__ x,
                     const float* __restrict__ w,
                     const float* __restrict__ s,
                     const float* __restrict__ t) {
    const int tid = threadIdx.x;
    const int m0 = blockIdx.y * BM;
    const int n0 = blockIdx.x * BN;

    if (g_flag) {
        // exact general path: 8 outputs per thread
        for (int e = tid; e < BM * BN; e += 256) {
            int b = m0 + (e >> 6);
            int o = n0 + (e & 63);
            const float* xr = x + (size_t)b * INF;
            const float* wr = w + (size_t)o * INF;
            const float* sr = s + (size_t)o * INF;
            const float* tr = t + (size_t)o * INF;
            float sum = 0.f;
            for (int i = 0; i < INF; ++i) {
                float z = (xr[i] - tr[i]) / sr[i];
                sum += wr[i] * (-z * __expf(-0.5f * z * z));
            }
            out[(size_t)b * OUTF + o] = sum;
        }
        return;
    }

    extern __shared__ char dsm[];
    const uint32_t sb = smem_u32(dsm);

    const int wid = tid >> 5, lid = tid & 31;
    const int wm = wid >> 2, wn = wid & 3;        // 2m x 4n warps, tile 16x16

    // 1536 cp.async of 16B per chunk, 6 per thread
    auto load_chunk = [&](int ci, int stage) {
        const int kc = ci * BK;
        const uint32_t st = sb + stage * STAGEB;
        #pragma unroll
        for (int it = 0; it < 6; it++) {
            int idx = tid + it * 256;
            if (idx < 512) {
                int r = idx >> 4;                // 0..31
                int q = idx & 15;
                const __half* g = g_phi_h + (size_t)(m0 + r) * INF + kc + q * 8;
                cp_async16(st + r * ROWB + q * 16, g);
            } else {
                int idx2 = idx - 512;
                int r = idx2 >> 4;               // 0..63
                int q = idx2 & 15;
                const __half* g = g_w_h + (size_t)(n0 + r) * INF + kc + q * 8;
                cp_async16(st + A_TILE + r * ROWB + q * 16, g);
            }
        }
        CP_COMMIT();
    };

    // accumulators split by k16 parity: [kspar][nb][4] -> 4 chains/warp
    float acc[2][2][4] = {{{0}}};

    load_chunk(0, 0);
    load_chunk(1, 1);

    const int a_row = wm * 16 + (lid & 15);
    const int a_colq = (lid >> 4) * 8;
    const int b_row7 = (lid & 7);
    const int b_colq = (lid >> 3) * 8;           // 0,8,16,24 over k32

    // fragment double buffers: [buf][ks][4] for A, [buf][nb][4] for B
    uint32_t af[2][2][4], bf[2][2][4];

    for (int ci = 0; ci < NCHUNK; ci++) {
        if (ci + 1 < NCHUNK) { CP_WAIT(1); } else { CP_WAIT(0); }
        __syncthreads();   // publish chunk ci; retire stage (ci-1)%3

        if (ci + 2 < NCHUNK) load_chunk(ci + 2, (ci + 2) % NSTAGE);

        const uint32_t sA = sb + (ci % NSTAGE) * STAGEB;
        const uint32_t sB = sA + A_TILE;

        // preload frags for kh=0
        {
            const int kb32 = 0;
            #pragma unroll
            for (int nb = 0; nb < 2; nb++) {
                const int brow = wn * 16 + nb * 8 + b_row7;
                ldm_x4(bf[0][nb][0], bf[0][nb][1], bf[0][nb][2], bf[0][nb][3],
                       sB + brow * ROWB + (kb32 + b_colq) * 2);
            }
            #pragma unroll
            for (int ks = 0; ks < 2; ks++)
                ldm_x4(af[0][ks][0], af[0][ks][1], af[0][ks][2], af[0][ks][3],
                       sA + a_row * ROWB + (kb32 + ks * 16 + a_colq) * 2);
        }

        #pragma unroll
        for (int kh = 0; kh < BK / 32; kh++) {   // 4 k32 groups
            const int cb = kh & 1, nx = cb ^ 1;
            // prefetch next k32 group's fragments
            if (kh + 1 < BK / 32) {
                const int kb32n = (kh + 1) * 32;
                #pragma unroll
                for (int nb = 0; nb < 2; nb++) {
                    const int brow = wn * 16 + nb * 8 + b_row7;
                    ldm_x4(bf[nx][nb][0], bf[nx][nb][1],
                           bf[nx][nb][2], bf[nx][nb][3],
                           sB + brow * ROWB + (kb32n + b_colq) * 2);
                }
                #pragma unroll
                for (int ks = 0; ks < 2; ks++)
                    ldm_x4(af[nx][ks][0], af[nx][ks][1],
                           af[nx][ks][2], af[nx][ks][3],
                           sA + a_row * ROWB + (kb32n + ks * 16 + a_colq) * 2);
            }
            // issue 8 MMAs for current group; acc chains split by ks parity
            #pragma unroll
            for (int ks = 0; ks < 2; ks++)
                #pragma unroll
                for (int nb = 0; nb < 2; nb++)
                    mma16816(acc[ks][nb], af[cb][ks], &bf[cb][nb][ks * 2]);
        }
    }

    const int row0 = m0 + wm * 16 + (lid >> 2);
    #pragma unroll
    for (int nb = 0; nb < 2; nb++) {
        const int col = n0 + wn * 16 + nb * 8 + (lid & 3) * 2;
        *reinterpret_cast<float2*>(&out[(size_t)row0 * OUTF + col]) =
            make_float2(acc[0][nb][0] + acc[1][nb][0],
                        acc[0][nb][1] + acc[1][nb][1]);
        *reinterpret_cast<float2*>(&out[(size_t)(row0 + 8) * OUTF + col]) =
            make_float2(acc[0][nb][2] + acc[1][nb][2],
                        acc[0][nb][3] + acc[1][nb][3]);
    }
}

extern "C" void kernel_launch(void* const* d_in, const int* in_sizes, int n_in,
                              void* d_out, int out_size) {
    const float* x     = (const float*)d_in[0];
    const float* wgt   = (const float*)d_in[1];
    const float* scale = (const float*)d_in[2];
    const float* trans = (const float*)d_in[3];
    float* out = (float*)d_out;

    static bool attr_set = false;
    if (!attr_set) {
        cudaFuncSetAttribute(mma_gemm_kernel,
                             cudaFuncAttributeMaxDynamicSharedMemorySize,
                             GEMM_SMEM);
        attr_set = true;
    }

    prep_kernel<<<W_BLOCKS + PHI_BLOCKS, 256>>>(
        (const float4*)wgt, (const float4*)x,
        (const float4*)scale, (const float4*)trans);
    mma_gemm_kernel<<<dim3(OUTF / BN, BATCH / BM), 256, GEMM_SMEM>>>(
        out, x, wgt, scale, trans);
}